// round 3
// baseline (speedup 1.0000x reference)
#include <cuda_runtime.h>
#include <cuda_bf16.h>
#include <math.h>

#define NN 64
#define BATCH 4096
#define EPS_PEN 0.1f
#define PEN_SCALE 1099511627776.0   // 2^40 fixed-point for deterministic atomic sum

__device__ unsigned long long g_acc;    // penalty accumulator (fixed-point)
__device__ unsigned int       g_count;  // completion counter (last-block-done)

// Block-wide (64-thread, 2-warp) sum reduction.
__device__ __forceinline__ float block_reduce64(float v, volatile float* red) {
    #pragma unroll
    for (int o = 16; o > 0; o >>= 1)
        v += __shfl_xor_sync(0xffffffffu, v, o);
    if ((threadIdx.x & 31) == 0) red[threadIdx.x >> 5] = v;
    __syncthreads();
    float r = red[0] + red[1];
    __syncthreads();
    return r;
}

__device__ void slow_path_eig(const float* __restrict__ src, int tid,
                              float M[NN][NN + 1], float* u, float* w,
                              float* dd, float* ee2, volatile float* red) {
    // ---- Load + sigmoid (hot in L2 from the min pass) ----
    for (int idx = tid; idx < NN * NN; idx += 64) {
        float x = src[idx];
        float s = 1.0f / (1.0f + expf(-x));
        M[idx >> 6][idx & 63] = s;
    }
    __syncthreads();

    float deg = 0.0f;
    #pragma unroll 8
    for (int j = 0; j < NN; j++) deg += M[tid][j];
    float aii = M[tid][tid];
    __syncthreads();

    for (int j = tid + 1; j < NN; j++) {
        float v = -0.5f * (M[tid][j] + M[j][tid]);
        M[tid][j] = v;
        M[j][tid] = v;
    }
    M[tid][tid] = deg - aii;
    __syncthreads();

    // ---- Householder tridiagonalization ----
    for (int k = 0; k < NN - 2; k++) {
        float xi = (tid > k) ? M[tid][k] : 0.0f;
        float sigma = block_reduce64(xi * xi, red);

        float x1 = M[k + 1][k];
        float nrm = sqrtf(sigma);
        float alpha = (x1 >= 0.0f) ? -nrm : nrm;
        if (tid == 0) ee2[k] = sigma;

        float vnorm2 = 2.0f * (sigma - x1 * alpha);
        float invv = 2.0f / fmaxf(vnorm2, 1e-30f);

        float vi = (tid > k) ? M[tid][k] : 0.0f;
        if (tid == k + 1) vi -= alpha;
        u[tid] = vi;
        __syncthreads();

        float pi = 0.0f;
        if (tid > k) {
            #pragma unroll 4
            for (int j = k + 1; j < NN; j++) pi += M[tid][j] * u[j];
            pi *= invv;
        }

        float s = block_reduce64(u[tid] * pi, red);
        float K = 0.5f * invv * s;
        w[tid] = pi - K * u[tid];
        __syncthreads();

        if (tid > k) {
            float vloc = u[tid];
            float wloc = w[tid];
            #pragma unroll 4
            for (int j = k + 1; j < NN; j++)
                M[tid][j] -= vloc * w[j] + wloc * u[j];
        }
        __syncthreads();
    }

    dd[tid] = M[tid][tid];
    if (tid == 0) {
        float t = M[NN - 1][NN - 2];
        ee2[NN - 2] = t * t;
        ee2[NN - 1] = 0.0f;
    }
    __syncthreads();

    // ---- Warp-0 multisection bisection for lambda_2 ----
    if (tid < 32) {
        float gl = 1e30f, gu = -1e30f;
        for (int i = tid; i < NN; i += 32) {
            float ei  = sqrtf(ee2[i]);
            float eim = (i > 0) ? sqrtf(ee2[i - 1]) : 0.0f;
            float r = ei + eim;
            gl = fminf(gl, dd[i] - r);
            gu = fmaxf(gu, dd[i] + r);
        }
        #pragma unroll
        for (int o = 16; o > 0; o >>= 1) {
            gl = fminf(gl, __shfl_xor_sync(0xffffffffu, gl, o));
            gu = fmaxf(gu, __shfl_xor_sync(0xffffffffu, gu, o));
        }

        float lo = gl, hi = gu;
        #pragma unroll 1
        for (int round = 0; round < 6; round++) {
            float stepw = (hi - lo) * (1.0f / 33.0f);
            float x = lo + stepw * (float)(tid + 1);
            float q = dd[0] - x;
            int c = (q < 0.0f);
            #pragma unroll 1
            for (int i = 1; i < NN; i++) {
                float den = q;
                if (fabsf(den) < 1e-30f) den = -1e-30f;
                q = dd[i] - x - ee2[i - 1] / den;
                c += (q < 0.0f);
            }
            unsigned bal = __ballot_sync(0xffffffffu, c >= 2);
            if (bal == 0u) {
                lo += stepw * 32.0f;
            } else {
                int t = __ffs(bal) - 1;
                hi = lo + stepw * (float)(t + 1);
                lo += stepw * (float)t;
            }
        }
        float lambda2 = 0.5f * (lo + hi);
        if (tid == 0) {
            float pen = fmaxf(0.0f, EPS_PEN - lambda2);
            unsigned long long q = (unsigned long long)((double)pen * PEN_SCALE);
            atomicAdd(&g_acc, q);   // order-independent => deterministic
        }
    }
    __syncthreads();
}

__global__ void __launch_bounds__(64)
spectral_kernel(const float* __restrict__ logits, float* __restrict__ out) {
    __shared__ float M[NN][NN + 1];
    __shared__ float u[NN];
    __shared__ float w[NN];
    __shared__ float dd[NN];
    __shared__ float ee2[NN];
    __shared__ float red[2];

    const int tid = threadIdx.x;
    const int b = blockIdx.x;
    const float* src = logits + (size_t)b * NN * NN;

    // ---- FAST PATH CHECK ----
    // lambda_2(M) >= NN * min_ij w_ij >= NN * sigmoid(min_ij x_ij)
    // (M - w_min * L_K64 is a Laplacian of nonneg weights => PSD.)
    // If bound >= EPS, penalty is exactly relu-clamped to 0 -> skip eigensolve.
    const float4* src4 = (const float4*)src;
    float xmin = 1e30f;
    #pragma unroll
    for (int i = 0; i < 16; i++) {
        float4 v = src4[tid + 64 * i];
        xmin = fminf(xmin, fminf(fminf(v.x, v.y), fminf(v.z, v.w)));
    }
    #pragma unroll
    for (int o = 16; o > 0; o >>= 1)
        xmin = fminf(xmin, __shfl_xor_sync(0xffffffffu, xmin, o));
    if ((tid & 31) == 0) red[tid >> 5] = xmin;
    __syncthreads();
    xmin = fminf(red[0], red[1]);   // uniform across block
    __syncthreads();                // red[] reused in slow path

    float bound = (float)NN / (1.0f + expf(-xmin));
    if (!(bound >= EPS_PEN)) {
        // rare: certified bound failed -> full eigensolve (adds to g_acc)
        slow_path_eig(src, tid, M, u, w, dd, ee2, red);
    }

    // ---- last-block-done: finalize without a second launch ----
    if (tid == 0) {
        __threadfence();   // make this block's g_acc contribution visible
        unsigned int old = atomicAdd(&g_count, 1u);
        if (old == BATCH - 1u) {
            __threadfence();
            unsigned long long a = g_acc;
            out[0] = (float)((double)a * (1.0 / PEN_SCALE) * (1.0 / (double)BATCH));
            g_acc = 0ull;     // reset for next graph replay
            __threadfence();
            g_count = 0u;
        }
    }
}

extern "C" void kernel_launch(void* const* d_in, const int* in_sizes, int n_in,
                              void* d_out, int out_size) {
    const float* logits = (const float*)d_in[0];   // [4096, 64, 64] float32
    // d_in[1] = node_types (int64) — unused by the reference computation
    float* out = (float*)d_out;

    spectral_kernel<<<BATCH, 64>>>(logits, out);
}

// round 4
// speedup vs baseline: 1.0902x; 1.0902x over previous
#include <cuda_runtime.h>
#include <cuda_bf16.h>
#include <math.h>

#define NN 64
#define BATCH 4096
#define BPB 2                    // batches per block
#define TPB 128                  // threads per block
#define GRID (BATCH / BPB)       // 2048
#define EPS_PEN 0.1f
// penalty == 0 certified iff xmin >= logit(EPS/NN) = -6.459905...; use tighter -6.4599
#define XMIN_THRESH -6.4599f
#define PEN_SCALE 1099511627776.0   // 2^40 fixed-point, order-independent accumulation

__device__ unsigned long long g_acc;    // fixed-point penalty accumulator
__device__ unsigned int       g_count;  // completion counter

// Block-wide (128-thread, 4-warp) sum reduction. All 128 threads must call.
__device__ __forceinline__ float block_reduce128(float v, volatile float* red) {
    #pragma unroll
    for (int o = 16; o > 0; o >>= 1)
        v += __shfl_xor_sync(0xffffffffu, v, o);
    if ((threadIdx.x & 31) == 0) red[threadIdx.x >> 5] = v;
    __syncthreads();
    float r = (red[0] + red[1]) + (red[2] + red[3]);
    __syncthreads();
    return r;
}

// Full eigensolve for one batch. ALL 128 threads enter (threads >= 64 idle at barriers).
__device__ void slow_path_eig(const float* __restrict__ src, int tid,
                              float M[NN][NN + 1], float* u, float* w,
                              float* dd, float* ee2, volatile float* red) {
    // ---- Load + sigmoid (hot in L2 from the min pass) ----
    for (int idx = tid; idx < NN * NN; idx += TPB) {
        float x = src[idx];
        float s = 1.0f / (1.0f + expf(-x));
        M[idx >> 6][idx & 63] = s;
    }
    __syncthreads();

    float deg = 0.0f, aii = 0.0f;
    if (tid < NN) {
        #pragma unroll 8
        for (int j = 0; j < NN; j++) deg += M[tid][j];
        aii = M[tid][tid];
    }
    __syncthreads();

    if (tid < NN) {
        for (int j = tid + 1; j < NN; j++) {
            float v = -0.5f * (M[tid][j] + M[j][tid]);
            M[tid][j] = v;
            M[j][tid] = v;
        }
        M[tid][tid] = deg - aii;
    }
    __syncthreads();

    // ---- Householder tridiagonalization ----
    for (int k = 0; k < NN - 2; k++) {
        float xi = (tid > k && tid < NN) ? M[tid][k] : 0.0f;
        float sigma = block_reduce128(xi * xi, red);

        float x1 = M[k + 1][k];
        float nrm = sqrtf(sigma);
        float alpha = (x1 >= 0.0f) ? -nrm : nrm;
        if (tid == 0) ee2[k] = sigma;

        float vnorm2 = 2.0f * (sigma - x1 * alpha);
        float invv = 2.0f / fmaxf(vnorm2, 1e-30f);

        if (tid < NN) {
            float vi = (tid > k) ? M[tid][k] : 0.0f;
            if (tid == k + 1) vi -= alpha;
            u[tid] = vi;
        }
        __syncthreads();

        float pi = 0.0f;
        if (tid > k && tid < NN) {
            #pragma unroll 4
            for (int j = k + 1; j < NN; j++) pi += M[tid][j] * u[j];
            pi *= invv;
        }

        float uv = (tid < NN) ? u[tid] : 0.0f;
        float s = block_reduce128(uv * pi, red);
        float K = 0.5f * invv * s;
        if (tid < NN) w[tid] = pi - K * uv;
        __syncthreads();

        if (tid > k && tid < NN) {
            float vloc = u[tid];
            float wloc = w[tid];
            #pragma unroll 4
            for (int j = k + 1; j < NN; j++)
                M[tid][j] -= vloc * w[j] + wloc * u[j];
        }
        __syncthreads();
    }

    if (tid < NN) dd[tid] = M[tid][tid];
    if (tid == 0) {
        float t = M[NN - 1][NN - 2];
        ee2[NN - 2] = t * t;
        ee2[NN - 1] = 0.0f;
    }
    __syncthreads();

    // ---- Warp-0 multisection bisection for lambda_2 ----
    if (tid < 32) {
        float gl = 1e30f, gu = -1e30f;
        for (int i = tid; i < NN; i += 32) {
            float ei  = sqrtf(ee2[i]);
            float eim = (i > 0) ? sqrtf(ee2[i - 1]) : 0.0f;
            float r = ei + eim;
            gl = fminf(gl, dd[i] - r);
            gu = fmaxf(gu, dd[i] + r);
        }
        #pragma unroll
        for (int o = 16; o > 0; o >>= 1) {
            gl = fminf(gl, __shfl_xor_sync(0xffffffffu, gl, o));
            gu = fmaxf(gu, __shfl_xor_sync(0xffffffffu, gu, o));
        }

        float lo = gl, hi = gu;
        #pragma unroll 1
        for (int round = 0; round < 6; round++) {
            float stepw = (hi - lo) * (1.0f / 33.0f);
            float x = lo + stepw * (float)(tid + 1);
            float q = dd[0] - x;
            int c = (q < 0.0f);
            #pragma unroll 1
            for (int i = 1; i < NN; i++) {
                float den = q;
                if (fabsf(den) < 1e-30f) den = -1e-30f;
                q = dd[i] - x - ee2[i - 1] / den;
                c += (q < 0.0f);
            }
            unsigned bal = __ballot_sync(0xffffffffu, c >= 2);
            if (bal == 0u) {
                lo += stepw * 32.0f;
            } else {
                int t = __ffs(bal) - 1;
                hi = lo + stepw * (float)(t + 1);
                lo += stepw * (float)t;
            }
        }
        float lambda2 = 0.5f * (lo + hi);
        if (tid == 0) {
            float pen = fmaxf(0.0f, EPS_PEN - lambda2);
            unsigned long long q = (unsigned long long)((double)pen * PEN_SCALE);
            atomicAdd(&g_acc, q);   // order-independent => deterministic
        }
    }
    __syncthreads();
}

__global__ void __launch_bounds__(TPB, 12)
spectral_kernel(const float* __restrict__ logits, float* __restrict__ out) {
    __shared__ float M[NN][NN + 1];
    __shared__ float u[NN];
    __shared__ float w[NN];
    __shared__ float dd[NN];
    __shared__ float ee2[NN];
    __shared__ float red[4];
    __shared__ float bmin[BPB];

    const int tid = threadIdx.x;
    const int sub = tid >> 6;        // which batch within the block (0..BPB-1)
    const int lane64 = tid & 63;
    const int b0 = blockIdx.x * BPB;
    const float4* src4 = (const float4*)(logits + (size_t)b0 * NN * NN);

    // ---- streaming per-batch min (the only work on the common path) ----
    float xmin = 1e30f;
    const int base = sub * 1024 + lane64;   // 1024 float4 per batch
    #pragma unroll
    for (int i = 0; i < 16; i++) {
        float4 v = src4[base + 64 * i];
        xmin = fminf(xmin, fminf(fminf(v.x, v.y), fminf(v.z, v.w)));
    }
    #pragma unroll
    for (int o = 16; o > 0; o >>= 1)
        xmin = fminf(xmin, __shfl_xor_sync(0xffffffffu, xmin, o));
    if ((tid & 31) == 0) red[tid >> 5] = xmin;   // warps 0,1 -> batch 0; warps 2,3 -> batch 1
    __syncthreads();
    if (tid < BPB) bmin[tid] = fminf(red[2 * tid], red[2 * tid + 1]);
    __syncthreads();

    // ---- certified bound: lambda_2 >= NN * sigmoid(xmin); penalty 0 if xmin >= THRESH ----
    bool contributed = false;
    #pragma unroll
    for (int s = 0; s < BPB; s++) {
        if (bmin[s] < XMIN_THRESH) {   // rare: full eigensolve for this batch
            slow_path_eig(logits + (size_t)(b0 + s) * NN * NN,
                          tid, M, u, w, dd, ee2, red);
            contributed = true;
        }
    }

    // ---- last-block-done finalize ----
    if (tid == 0) {
        if (contributed) __threadfence();
        unsigned int old = atomicAdd(&g_count, 1u);
        if (old == GRID - 1u) {
            __threadfence();
            unsigned long long a = g_acc;
            out[0] = (float)((double)a * (1.0 / PEN_SCALE) * (1.0 / (double)BATCH));
            g_acc = 0ull;     // reset for next graph replay
            __threadfence();
            g_count = 0u;
        }
    }
}

extern "C" void kernel_launch(void* const* d_in, const int* in_sizes, int n_in,
                              void* d_out, int out_size) {
    const float* logits = (const float*)d_in[0];   // [4096, 64, 64] float32
    // d_in[1] = node_types (int64) — unused by the reference computation
    float* out = (float*)d_out;

    spectral_kernel<<<GRID, TPB>>>(logits, out);
}